// round 2
// baseline (speedup 1.0000x reference)
#include <cuda_runtime.h>
#include <math.h>

// Problem constants
#define BB 4
#define CC 256
#define NN 4096     // H*W = 64*64
#define NHEAD 4
#define HD 64
#define GROUPS 32
#define CPG 8       // C / GROUPS
#define EPSV 1e-5f

// Scratch (allocation-free rule: __device__ globals)
__device__ float g_qin [BB*CC*NN];
__device__ float g_kvin[BB*CC*NN];
__device__ float g_q   [BB*CC*NN];
__device__ float g_k   [BB*CC*NN];
__device__ float g_v   [BB*CC*NN];
__device__ float g_att [BB*CC*NN];

// ---------------------------------------------------------------------------
// GroupNorm: one block per (batch, group). Normalize over CPG*N elements.
// ---------------------------------------------------------------------------
__global__ void gn_kernel(const float* __restrict__ x,
                          const float* __restrict__ gamma,
                          const float* __restrict__ beta,
                          float* __restrict__ out) {
    int b = blockIdx.x / GROUPS;
    int g = blockIdx.x % GROUPS;
    const int M = CPG * NN;  // 32768
    size_t base = (size_t)b * CC * NN + (size_t)g * CPG * NN;
    const float* xp = x + base;

    float s = 0.f, ss = 0.f;
    for (int i = threadIdx.x; i < M; i += blockDim.x) {
        float v = xp[i];
        s += v; ss += v * v;
    }
    __shared__ float rs[256], rq[256];
    rs[threadIdx.x] = s; rq[threadIdx.x] = ss;
    __syncthreads();
    for (int o = 128; o > 0; o >>= 1) {
        if (threadIdx.x < o) {
            rs[threadIdx.x] += rs[threadIdx.x + o];
            rq[threadIdx.x] += rq[threadIdx.x + o];
        }
        __syncthreads();
    }
    float mean = rs[0] / (float)M;
    float var  = rq[0] / (float)M - mean * mean;
    float rstd = rsqrtf(var + EPSV);

    float* op = out + base;
    for (int i = threadIdx.x; i < M; i += blockDim.x) {
        int c = g * CPG + (i >> 12);   // i / NN
        op[i] = (xp[i] - mean) * rstd * gamma[c] + beta[c];
    }
}

// ---------------------------------------------------------------------------
// conv1x1 as batched GEMM: out[b,o,n] = sum_c w[o,c] * in[b,c,n] + bias[o]
// (+ optional residual). 64x64 tile per block, 4x4 per thread, K-tile = 16.
// grid = (N/64, C/64, B), block = 256.
// ---------------------------------------------------------------------------
__global__ void conv_kernel(const float* __restrict__ in,
                            const float* __restrict__ w,
                            const float* __restrict__ bias,
                            const float* __restrict__ res,
                            float* __restrict__ out) {
    __shared__ float As[16][64];  // [k][o]
    __shared__ float Bs[16][64];  // [k][n]
    int bn = blockIdx.x, bo = blockIdx.y, b = blockIdx.z;
    int tid = threadIdx.x;
    int tx = tid & 15, ty = tid >> 4;
    const float* inp = in + (size_t)b * CC * NN + bn * 64;

    float acc[4][4] = {};
    for (int kt = 0; kt < CC; kt += 16) {
        __syncthreads();
        #pragma unroll
        for (int l = 0; l < 4; l++) {
            int e = tid + l * 256;
            int k = e >> 6, m = e & 63;
            As[k][m] = w[(size_t)(bo * 64 + m) * CC + kt + k];
            Bs[k][m] = inp[(size_t)(kt + k) * NN + m];
        }
        __syncthreads();
        #pragma unroll
        for (int kk = 0; kk < 16; kk++) {
            float4 a = *(const float4*)&As[kk][ty * 4];
            float4 c4 = *(const float4*)&Bs[kk][tx * 4];
            float av[4] = {a.x, a.y, a.z, a.w};
            float bv[4] = {c4.x, c4.y, c4.z, c4.w};
            #pragma unroll
            for (int i = 0; i < 4; i++)
                #pragma unroll
                for (int j = 0; j < 4; j++)
                    acc[i][j] += av[i] * bv[j];
        }
    }
    #pragma unroll
    for (int i = 0; i < 4; i++) {
        int o = bo * 64 + ty * 4 + i;
        float bi = bias[o];
        #pragma unroll
        for (int j = 0; j < 4; j++) {
            size_t idx = ((size_t)b * CC + o) * NN + bn * 64 + tx * 4 + j;
            float v = acc[i][j] + bi;
            if (res) v += res[idx];
            out[idx] = v;
        }
    }
}

// ---------------------------------------------------------------------------
// Flash-style attention. q,k,v: [B][C][N] with channel = h*HD + d.
// One block per (query-tile of 64, head, batch). 256 threads, 4x4 micro-tile.
// ---------------------------------------------------------------------------
__global__ void attn_kernel(const float* __restrict__ q,
                            const float* __restrict__ k,
                            const float* __restrict__ v,
                            float* __restrict__ out) {
    extern __shared__ float sm[];
    float* Qs = sm;                // [64][64]  d-major  (Qs[d*64+q])
    float* Ks = Qs + 64 * 64;      // [64][64]  d-major
    float* Vs = Ks + 64 * 64;      // [64][68]  m-major, padded (Vs[m*68+d])
    float* Ps = Vs + 64 * 68;      // [64][66]  q-major, padded (Ps[q*66+m])

    int nb = blockIdx.x;           // query tile
    int h  = blockIdx.y;
    int b  = blockIdx.z;
    int tid = threadIdx.x;
    int tx = tid & 15, ty = tid >> 4;
    size_t base = ((size_t)b * CC + h * HD) * NN;
    int n0 = nb * 64;

    // Load Q tile (coalesced over n)
    #pragma unroll
    for (int l = 0; l < 16; l++) {
        int e = tid + l * 256;
        int d = e >> 6, qn = e & 63;
        Qs[d * 64 + qn] = q[base + (size_t)d * NN + n0 + qn];
    }

    float acc[4][4] = {};
    float mi[4], li[4];
    #pragma unroll
    for (int i = 0; i < 4; i++) { mi[i] = -1e30f; li[i] = 0.f; }
    const float scale = 0.125f;    // hd^-0.5 = 1/8

    for (int mt = 0; mt < NN; mt += 64) {
        __syncthreads();
        #pragma unroll
        for (int l = 0; l < 16; l++) {
            int e = tid + l * 256;
            int d = e >> 6, m = e & 63;
            float kvv = k[base + (size_t)d * NN + mt + m];
            float vvv = v[base + (size_t)d * NN + mt + m];
            Ks[d * 64 + m] = kvv;
            Vs[m * 68 + d] = vvv;     // transposed store (4-way conflict, ok)
        }
        __syncthreads();

        // S = Q^T K (64x64), scaled
        float s[4][4] = {};
        #pragma unroll 8
        for (int d = 0; d < 64; d++) {
            float4 qa = *(const float4*)&Qs[d * 64 + ty * 4];
            float4 ka = *(const float4*)&Ks[d * 64 + tx * 4];
            float qv[4] = {qa.x, qa.y, qa.z, qa.w};
            float kv[4] = {ka.x, ka.y, ka.z, ka.w};
            #pragma unroll
            for (int i = 0; i < 4; i++)
                #pragma unroll
                for (int j = 0; j < 4; j++)
                    s[i][j] += qv[i] * kv[j];
        }

        // Online softmax per query row (reduce across the 16 tx lanes)
        #pragma unroll
        for (int i = 0; i < 4; i++) {
            float rm = -1e30f;
            #pragma unroll
            for (int j = 0; j < 4; j++) { s[i][j] *= scale; rm = fmaxf(rm, s[i][j]); }
            #pragma unroll
            for (int o2 = 8; o2 >= 1; o2 >>= 1)
                rm = fmaxf(rm, __shfl_xor_sync(0xffffffffu, rm, o2));
            float newm = fmaxf(mi[i], rm);
            float corr = __expf(mi[i] - newm);
            mi[i] = newm;
            float rsum = 0.f;
            #pragma unroll
            for (int j = 0; j < 4; j++) { s[i][j] = __expf(s[i][j] - newm); rsum += s[i][j]; }
            #pragma unroll
            for (int o2 = 8; o2 >= 1; o2 >>= 1)
                rsum += __shfl_xor_sync(0xffffffffu, rsum, o2);
            li[i] = li[i] * corr + rsum;
            #pragma unroll
            for (int j = 0; j < 4; j++) {
                acc[i][j] *= corr;
                Ps[(ty * 4 + i) * 66 + tx * 4 + j] = s[i][j];
            }
        }
        __syncthreads();

        // O += P V^T : O[q][d] += sum_m P[q][m] * V[m][d]
        #pragma unroll 8
        for (int m = 0; m < 64; m++) {
            float4 va = *(const float4*)&Vs[m * 68 + tx * 4];
            float vv[4] = {va.x, va.y, va.z, va.w};
            float pv[4];
            #pragma unroll
            for (int i = 0; i < 4; i++) pv[i] = Ps[(ty * 4 + i) * 66 + m];
            #pragma unroll
            for (int i = 0; i < 4; i++)
                #pragma unroll
                for (int j = 0; j < 4; j++)
                    acc[i][j] += pv[i] * vv[j];
        }
    }
    __syncthreads();

    // Normalize and stage (reuse Qs as [d][q]) for coalesced writeback
    #pragma unroll
    for (int i = 0; i < 4; i++) {
        float inv = 1.f / li[i];
        #pragma unroll
        for (int j = 0; j < 4; j++)
            Qs[(tx * 4 + j) * 64 + ty * 4 + i] = acc[i][j] * inv;
    }
    __syncthreads();
    #pragma unroll
    for (int l = 0; l < 16; l++) {
        int e = tid + l * 256;
        int d = e >> 6, qn = e & 63;
        out[base + (size_t)d * NN + n0 + qn] = Qs[d * 64 + qn];
    }
}

// ---------------------------------------------------------------------------
extern "C" void kernel_launch(void* const* d_in, const int* in_sizes, int n_in,
                              void* d_out, int out_size) {
    const float* x      = (const float*)d_in[0];
    const float* cond   = (const float*)d_in[1];
    const float* gn_q_w = (const float*)d_in[2];
    const float* gn_q_b = (const float*)d_in[3];
    const float* gn_kv_w= (const float*)d_in[4];
    const float* gn_kv_b= (const float*)d_in[5];
    const float* wq     = (const float*)d_in[6];
    const float* bq     = (const float*)d_in[7];
    const float* wk     = (const float*)d_in[8];
    const float* bk     = (const float*)d_in[9];
    const float* wv     = (const float*)d_in[10];
    const float* bv     = (const float*)d_in[11];
    const float* wo     = (const float*)d_in[12];
    const float* bo     = (const float*)d_in[13];
    float* out = (float*)d_out;

    float *qin, *kvin, *qb, *kb, *vb, *attb;
    cudaGetSymbolAddress((void**)&qin,  g_qin);
    cudaGetSymbolAddress((void**)&kvin, g_kvin);
    cudaGetSymbolAddress((void**)&qb,   g_q);
    cudaGetSymbolAddress((void**)&kb,   g_k);
    cudaGetSymbolAddress((void**)&vb,   g_v);
    cudaGetSymbolAddress((void**)&attb, g_att);

    // GroupNorms
    gn_kernel<<<BB * GROUPS, 256>>>(x,    gn_q_w,  gn_q_b,  qin);
    gn_kernel<<<BB * GROUPS, 256>>>(cond, gn_kv_w, gn_kv_b, kvin);

    // q / k / v projections
    dim3 cgrid(NN / 64, CC / 64, BB);
    conv_kernel<<<cgrid, 256>>>(qin,  wq, bq, nullptr, qb);
    conv_kernel<<<cgrid, 256>>>(kvin, wk, bk, nullptr, kb);
    conv_kernel<<<cgrid, 256>>>(kvin, wv, bv, nullptr, vb);

    // Attention
    int smem = (64*64 + 64*64 + 64*68 + 64*66) * (int)sizeof(float); // 67072 B
    cudaFuncSetAttribute(attn_kernel, cudaFuncAttributeMaxDynamicSharedMemorySize, smem);
    dim3 agrid(NN / 64, NHEAD, BB);
    attn_kernel<<<agrid, 256, smem>>>(qb, kb, vb, attb);

    // Output projection + residual
    conv_kernel<<<cgrid, 256>>>(attb, wo, bo, x, out);
}

// round 4
// speedup vs baseline: 2.2739x; 2.2739x over previous
#include <cuda_runtime.h>
#include <math.h>

#define BB 4
#define CC 256
#define NN 4096
#define NHEAD 4
#define HD 64
#define GROUPS 32
#define CPG 8
#define EPSV 1e-5f

__device__ float g_qin [BB*CC*NN];
__device__ float g_kvin[BB*CC*NN];
__device__ float g_q   [BB*CC*NN];
__device__ float g_k   [BB*CC*NN];
__device__ float g_v   [BB*CC*NN];
__device__ float g_att [BB*CC*NN];

// ---------------------------------------------------------------------------
__device__ __forceinline__ unsigned f2tf(float x) {
    unsigned u;
    asm("cvt.rna.tf32.f32 %0, %1;" : "=r"(u) : "f"(x));
    return u;
}
__device__ __forceinline__ float f2tff(float x) { return __uint_as_float(f2tf(x)); }
__device__ __forceinline__ unsigned uf(float x) { return __float_as_uint(x); }

__device__ __forceinline__ void mma_tf32(float c[4],
                                         unsigned a0, unsigned a1, unsigned a2, unsigned a3,
                                         unsigned b0, unsigned b1) {
    asm volatile(
        "mma.sync.aligned.m16n8k8.row.col.f32.tf32.tf32.f32 "
        "{%0,%1,%2,%3}, {%4,%5,%6,%7}, {%8,%9}, {%0,%1,%2,%3};"
        : "+f"(c[0]), "+f"(c[1]), "+f"(c[2]), "+f"(c[3])
        : "r"(a0), "r"(a1), "r"(a2), "r"(a3), "r"(b0), "r"(b1));
}

// ---------------------------------------------------------------------------
// GroupNorm: one block per (batch, group).
// ---------------------------------------------------------------------------
__global__ void gn_kernel(const float* __restrict__ x,
                          const float* __restrict__ gamma,
                          const float* __restrict__ beta,
                          float* __restrict__ out) {
    int b = blockIdx.x / GROUPS;
    int g = blockIdx.x % GROUPS;
    const int M = CPG * NN;
    size_t base = (size_t)b * CC * NN + (size_t)g * CPG * NN;
    const float* xp = x + base;

    float s = 0.f, ss = 0.f;
    for (int i = threadIdx.x; i < M; i += blockDim.x) {
        float v = xp[i];
        s += v; ss += v * v;
    }
    __shared__ float rs[256], rq[256];
    rs[threadIdx.x] = s; rq[threadIdx.x] = ss;
    __syncthreads();
    for (int o = 128; o > 0; o >>= 1) {
        if (threadIdx.x < o) {
            rs[threadIdx.x] += rs[threadIdx.x + o];
            rq[threadIdx.x] += rq[threadIdx.x + o];
        }
        __syncthreads();
    }
    float mean = rs[0] / (float)M;
    float var  = rq[0] / (float)M - mean * mean;
    float rstd = rsqrtf(var + EPSV);

    float* op = out + base;
    for (int i = threadIdx.x; i < M; i += blockDim.x) {
        int c = g * CPG + (i >> 12);
        op[i] = (xp[i] - mean) * rstd * gamma[c] + beta[c];
    }
}

// ---------------------------------------------------------------------------
// conv1x1 via tf32 mma: out[b,o,n] = W[o,:]·In[b,:,n] + bias (+res)
// grid (NN/64, CC/64, B), 128 threads = 4 warps, warp = 16 o-rows x 64 n.
// ---------------------------------------------------------------------------
__global__ __launch_bounds__(128) void conv_mma(const float* __restrict__ in,
                                                const float* __restrict__ w,
                                                const float* __restrict__ bias,
                                                const float* __restrict__ res,
                                                float* __restrict__ out) {
    __shared__ float Ws[64 * 36];   // [o][k] stride 36
    __shared__ float Bs[32 * 72];   // [k][n] stride 72
    int bn = blockIdx.x, bo = blockIdx.y, b = blockIdx.z;
    int tid = threadIdx.x, lane = tid & 31, warp = tid >> 5;
    int g = lane >> 2, c = lane & 3;
    int ow = warp * 16;
    const float* inp = in + (size_t)b * CC * NN + bn * 64;

    float acc[8][4] = {};
    for (int kt = 0; kt < CC; kt += 32) {
        __syncthreads();
        #pragma unroll
        for (int e = tid; e < 2048; e += 128) {
            int o = e >> 5, kk = e & 31;
            Ws[o * 36 + kk] = f2tff(w[(size_t)(bo * 64 + o) * CC + kt + kk]);
        }
        #pragma unroll
        for (int e = tid; e < 2048; e += 128) {
            int kk = e >> 6, n = e & 63;
            Bs[kk * 72 + n] = f2tff(inp[(size_t)(kt + kk) * NN + n]);
        }
        __syncthreads();
        #pragma unroll
        for (int ks = 0; ks < 4; ks++) {
            unsigned a0 = uf(Ws[(ow + g) * 36 + ks * 8 + c]);
            unsigned a1 = uf(Ws[(ow + g + 8) * 36 + ks * 8 + c]);
            unsigned a2 = uf(Ws[(ow + g) * 36 + ks * 8 + c + 4]);
            unsigned a3 = uf(Ws[(ow + g + 8) * 36 + ks * 8 + c + 4]);
            #pragma unroll
            for (int nt = 0; nt < 8; nt++) {
                unsigned b0 = uf(Bs[(ks * 8 + c) * 72 + nt * 8 + g]);
                unsigned b1 = uf(Bs[(ks * 8 + c + 4) * 72 + nt * 8 + g]);
                mma_tf32(acc[nt], a0, a1, a2, a3, b0, b1);
            }
        }
    }
    int o0 = bo * 64 + ow + g;
    float bi0 = bias[o0], bi1 = bias[o0 + 8];
    #pragma unroll
    for (int nt = 0; nt < 8; nt++) {
        int n = bn * 64 + nt * 8 + 2 * c;
        size_t i0 = ((size_t)b * CC + o0) * NN + n;
        size_t i1 = ((size_t)b * CC + o0 + 8) * NN + n;
        float2 v0 = make_float2(acc[nt][0] + bi0, acc[nt][1] + bi0);
        float2 v1 = make_float2(acc[nt][2] + bi1, acc[nt][3] + bi1);
        if (res) {
            float2 r0 = *(const float2*)&res[i0];
            float2 r1 = *(const float2*)&res[i1];
            v0.x += r0.x; v0.y += r0.y;
            v1.x += r1.x; v1.y += r1.y;
        }
        *(float2*)&out[i0] = v0;
        *(float2*)&out[i1] = v1;
    }
}

// ---------------------------------------------------------------------------
// Flash attention, tf32 mma. Block = 128 queries x one head. 256 thr = 8 warps.
// Warp owns 16 query rows x all 64 keys of the current tile.
// q,k,v: [B][C][N] d-major per head.
// ---------------------------------------------------------------------------
__global__ __launch_bounds__(256, 1) void attn_mma(const float* __restrict__ q,
                                                   const float* __restrict__ k,
                                                   const float* __restrict__ v,
                                                   float* __restrict__ out) {
    extern __shared__ float sm[];
    float* Qs = sm;               // [128 q][68]  (q-major, tf32, pre-scaled)
    float* Kd = Qs + 128 * 68;    // [64 d][72]
    float* Vd = Kd + 64 * 72;     // [64 d][76]
    float* Os = Kd;               // [64 d][132]  (reuses Kd+Vd at end)

    int nb = blockIdx.x, h = blockIdx.y, b = blockIdx.z;
    int tid = threadIdx.x, lane = tid & 31, warp = tid >> 5;
    int g = lane >> 2, c = lane & 3;
    int qw = warp * 16;
    size_t base = ((size_t)b * CC + h * HD) * NN;
    int n0 = nb * 128;

    // Load Q (scaled by hd^-0.5 = 1/8), tf32-rounded
    for (int e = tid; e < 64 * 128; e += 256) {
        int d = e >> 7, qn = e & 127;
        Qs[qn * 68 + d] = f2tff(q[base + (size_t)d * NN + n0 + qn] * 0.125f);
    }
    __syncthreads();

    // Q A-fragments, persistent in registers
    unsigned qa[8][4];
    #pragma unroll
    for (int kt = 0; kt < 8; kt++) {
        qa[kt][0] = uf(Qs[(qw + g) * 68 + kt * 8 + c]);
        qa[kt][1] = uf(Qs[(qw + g + 8) * 68 + kt * 8 + c]);
        qa[kt][2] = uf(Qs[(qw + g) * 68 + kt * 8 + c + 4]);
        qa[kt][3] = uf(Qs[(qw + g + 8) * 68 + kt * 8 + c + 4]);
    }

    float o[8][4] = {};
    float m0 = -1e30f, m1 = -1e30f, l0 = 0.f, l1 = 0.f;

    for (int mt = 0; mt < NN; mt += 64) {
        __syncthreads();
        for (int e = tid; e < 4096; e += 256) {
            int d = e >> 6, mm = e & 63;
            Kd[d * 72 + mm] = f2tff(k[base + (size_t)d * NN + mt + mm]);
            Vd[d * 76 + mm] = f2tff(v[base + (size_t)d * NN + mt + mm]);
        }
        __syncthreads();

        // S = Q K^T  (warp: 16 q x 64 keys)
        float s[8][4] = {};
        #pragma unroll
        for (int kt = 0; kt < 8; kt++) {
            #pragma unroll
            for (int nt = 0; nt < 8; nt++) {
                unsigned b0 = uf(Kd[(kt * 8 + c) * 72 + nt * 8 + g]);
                unsigned b1 = uf(Kd[(kt * 8 + c + 4) * 72 + nt * 8 + g]);
                mma_tf32(s[nt], qa[kt][0], qa[kt][1], qa[kt][2], qa[kt][3], b0, b1);
            }
        }

        // Online softmax (rows g and g+8; stats shared by the 4 lanes of a group)
        float rmax0 = -1e30f, rmax1 = -1e30f;
        #pragma unroll
        for (int nt = 0; nt < 8; nt++) {
            rmax0 = fmaxf(rmax0, fmaxf(s[nt][0], s[nt][1]));
            rmax1 = fmaxf(rmax1, fmaxf(s[nt][2], s[nt][3]));
        }
        rmax0 = fmaxf(rmax0, __shfl_xor_sync(0xffffffffu, rmax0, 1));
        rmax0 = fmaxf(rmax0, __shfl_xor_sync(0xffffffffu, rmax0, 2));
        rmax1 = fmaxf(rmax1, __shfl_xor_sync(0xffffffffu, rmax1, 1));
        rmax1 = fmaxf(rmax1, __shfl_xor_sync(0xffffffffu, rmax1, 2));
        float nm0 = fmaxf(m0, rmax0), nm1 = fmaxf(m1, rmax1);
        float cor0 = __expf(m0 - nm0), cor1 = __expf(m1 - nm1);
        m0 = nm0; m1 = nm1;

        float rs0 = 0.f, rs1 = 0.f;
        unsigned pu[8][4];
        #pragma unroll
        for (int nt = 0; nt < 8; nt++) {
            float p0 = __expf(s[nt][0] - nm0);
            float p1 = __expf(s[nt][1] - nm0);
            float p2 = __expf(s[nt][2] - nm1);
            float p3 = __expf(s[nt][3] - nm1);
            rs0 += p0 + p1; rs1 += p2 + p3;
            pu[nt][0] = f2tf(p0); pu[nt][1] = f2tf(p1);
            pu[nt][2] = f2tf(p2); pu[nt][3] = f2tf(p3);
        }
        rs0 += __shfl_xor_sync(0xffffffffu, rs0, 1);
        rs0 += __shfl_xor_sync(0xffffffffu, rs0, 2);
        rs1 += __shfl_xor_sync(0xffffffffu, rs1, 1);
        rs1 += __shfl_xor_sync(0xffffffffu, rs1, 2);
        l0 = l0 * cor0 + rs0;
        l1 = l1 * cor1 + rs1;
        #pragma unroll
        for (int nt = 0; nt < 8; nt++) {
            o[nt][0] *= cor0; o[nt][1] *= cor0;
            o[nt][2] *= cor1; o[nt][3] *= cor1;
        }

        // O += P V : convert P c-layout -> a-layout via shfl, then mma
        int basel = lane & ~3;
        int s1 = basel | (c >> 1);
        int s2 = basel | ((c >> 1) + 2);
        int sel = lane & 1;
        #pragma unroll
        for (int j = 0; j < 8; j++) {
            unsigned v00 = __shfl_sync(0xffffffffu, pu[j][0], s1);
            unsigned v01 = __shfl_sync(0xffffffffu, pu[j][1], s1);
            unsigned v10 = __shfl_sync(0xffffffffu, pu[j][2], s1);
            unsigned v11 = __shfl_sync(0xffffffffu, pu[j][3], s1);
            unsigned v20 = __shfl_sync(0xffffffffu, pu[j][0], s2);
            unsigned v21 = __shfl_sync(0xffffffffu, pu[j][1], s2);
            unsigned v30 = __shfl_sync(0xffffffffu, pu[j][2], s2);
            unsigned v31 = __shfl_sync(0xffffffffu, pu[j][3], s2);
            unsigned a0 = sel ? v01 : v00;
            unsigned a1 = sel ? v11 : v10;
            unsigned a2 = sel ? v21 : v20;
            unsigned a3 = sel ? v31 : v30;
            #pragma unroll
            for (int nt = 0; nt < 8; nt++) {
                unsigned b0 = uf(Vd[(nt * 8 + g) * 76 + j * 8 + c]);
                unsigned b1 = uf(Vd[(nt * 8 + g) * 76 + j * 8 + c + 4]);
                mma_tf32(o[nt], a0, a1, a2, a3, b0, b1);
            }
        }
    }
    __syncthreads();

    // Normalize, stage d-major in smem, coalesced writeback
    float inv0 = 1.f / l0, inv1 = 1.f / l1;
    #pragma unroll
    for (int nt = 0; nt < 8; nt++) {
        int d = nt * 8 + 2 * c;
        Os[d * 132 + qw + g]           = o[nt][0] * inv0;
        Os[(d + 1) * 132 + qw + g]     = o[nt][1] * inv0;
        Os[d * 132 + qw + g + 8]       = o[nt][2] * inv1;
        Os[(d + 1) * 132 + qw + g + 8] = o[nt][3] * inv1;
    }
    __syncthreads();
    for (int e = tid; e < 64 * 128; e += 256) {
        int d = e >> 7, qn = e & 127;
        out[base + (size_t)d * NN + n0 + qn] = Os[d * 132 + qn];
    }
}

// ---------------------------------------------------------------------------
extern "C" void kernel_launch(void* const* d_in, const int* in_sizes, int n_in,
                              void* d_out, int out_size) {
    const float* x      = (const float*)d_in[0];
    const float* cond   = (const float*)d_in[1];
    const float* gn_q_w = (const float*)d_in[2];
    const float* gn_q_b = (const float*)d_in[3];
    const float* gn_kv_w= (const float*)d_in[4];
    const float* gn_kv_b= (const float*)d_in[5];
    const float* wq     = (const float*)d_in[6];
    const float* bq     = (const float*)d_in[7];
    const float* wk     = (const float*)d_in[8];
    const float* bk     = (const float*)d_in[9];
    const float* wv     = (const float*)d_in[10];
    const float* bv     = (const float*)d_in[11];
    const float* wo     = (const float*)d_in[12];
    const float* bo     = (const float*)d_in[13];
    float* out = (float*)d_out;

    float *qin, *kvin, *qb, *kb, *vb, *attb;
    cudaGetSymbolAddress((void**)&qin,  g_qin);
    cudaGetSymbolAddress((void**)&kvin, g_kvin);
    cudaGetSymbolAddress((void**)&qb,   g_q);
    cudaGetSymbolAddress((void**)&kb,   g_k);
    cudaGetSymbolAddress((void**)&vb,   g_v);
    cudaGetSymbolAddress((void**)&attb, g_att);

    gn_kernel<<<BB * GROUPS, 256>>>(x,    gn_q_w,  gn_q_b,  qin);
    gn_kernel<<<BB * GROUPS, 256>>>(cond, gn_kv_w, gn_kv_b, kvin);

    dim3 cgrid(NN / 64, CC / 64, BB);
    conv_mma<<<cgrid, 128>>>(qin,  wq, bq, nullptr, qb);
    conv_mma<<<cgrid, 128>>>(kvin, wk, bk, nullptr, kb);
    conv_mma<<<cgrid, 128>>>(kvin, wv, bv, nullptr, vb);

    int smem = (128 * 68 + 64 * 72 + 64 * 76) * (int)sizeof(float); // 72704 B
    cudaFuncSetAttribute(attn_mma, cudaFuncAttributeMaxDynamicSharedMemorySize, smem);
    dim3 agrid(NN / 128, NHEAD, BB);
    attn_mma<<<agrid, 256, smem>>>(qb, kb, vb, attb);

    conv_mma<<<cgrid, 128>>>(attb, wo, bo, x, out);
}

// round 5
// speedup vs baseline: 4.1702x; 1.8339x over previous
#include <cuda_runtime.h>
#include <cuda_bf16.h>
#include <math.h>

#define BB 4
#define CC 256
#define NN 4096
#define NHEAD 4
#define HD 64
#define GROUPS 32
#define CPG 8
#define EPSV 1e-5f

__device__ float g_qin [BB*CC*NN];
__device__ float g_kvin[BB*CC*NN];
__device__ float g_q   [BB*CC*NN];
__device__ float g_k   [BB*CC*NN];
__device__ float g_v   [BB*CC*NN];
__device__ float g_att [BB*CC*NN];

// ---------------------------------------------------------------------------
__device__ __forceinline__ unsigned f2tf(float x) {
    unsigned u;
    asm("cvt.rna.tf32.f32 %0, %1;" : "=r"(u) : "f"(x));
    return u;
}
__device__ __forceinline__ float f2tff(float x) { return __uint_as_float(f2tf(x)); }
__device__ __forceinline__ unsigned uf(float x) { return __float_as_uint(x); }

// pack two f32 -> bf16x2 (lo = first elem, hi = second)
__device__ __forceinline__ unsigned pk_bf2(float lo, float hi) {
    unsigned r;
    asm("cvt.rn.bf16x2.f32 %0, %1, %2;" : "=r"(r) : "f"(hi), "f"(lo));
    return r;
}

__device__ __forceinline__ void mma_tf32(float c[4],
                                         unsigned a0, unsigned a1, unsigned a2, unsigned a3,
                                         unsigned b0, unsigned b1) {
    asm volatile(
        "mma.sync.aligned.m16n8k8.row.col.f32.tf32.tf32.f32 "
        "{%0,%1,%2,%3}, {%4,%5,%6,%7}, {%8,%9}, {%0,%1,%2,%3};"
        : "+f"(c[0]), "+f"(c[1]), "+f"(c[2]), "+f"(c[3])
        : "r"(a0), "r"(a1), "r"(a2), "r"(a3), "r"(b0), "r"(b1));
}

__device__ __forceinline__ void mma_bf16(float c[4],
                                         unsigned a0, unsigned a1, unsigned a2, unsigned a3,
                                         unsigned b0, unsigned b1) {
    asm volatile(
        "mma.sync.aligned.m16n8k16.row.col.f32.bf16.bf16.f32 "
        "{%0,%1,%2,%3}, {%4,%5,%6,%7}, {%8,%9}, {%0,%1,%2,%3};"
        : "+f"(c[0]), "+f"(c[1]), "+f"(c[2]), "+f"(c[3])
        : "r"(a0), "r"(a1), "r"(a2), "r"(a3), "r"(b0), "r"(b1));
}

// ---------------------------------------------------------------------------
// GroupNorm: one block per (batch, group).
// ---------------------------------------------------------------------------
__global__ void gn_kernel(const float* __restrict__ x,
                          const float* __restrict__ gamma,
                          const float* __restrict__ beta,
                          float* __restrict__ out) {
    int b = blockIdx.x / GROUPS;
    int g = blockIdx.x % GROUPS;
    const int M = CPG * NN;
    size_t base = (size_t)b * CC * NN + (size_t)g * CPG * NN;
    const float* xp = x + base;

    float s = 0.f, ss = 0.f;
    for (int i = threadIdx.x; i < M; i += blockDim.x) {
        float v = xp[i];
        s += v; ss += v * v;
    }
    __shared__ float rs[256], rq[256];
    rs[threadIdx.x] = s; rq[threadIdx.x] = ss;
    __syncthreads();
    for (int o = 128; o > 0; o >>= 1) {
        if (threadIdx.x < o) {
            rs[threadIdx.x] += rs[threadIdx.x + o];
            rq[threadIdx.x] += rq[threadIdx.x + o];
        }
        __syncthreads();
    }
    float mean = rs[0] / (float)M;
    float var  = rq[0] / (float)M - mean * mean;
    float rstd = rsqrtf(var + EPSV);

    float* op = out + base;
    for (int i = threadIdx.x; i < M; i += blockDim.x) {
        int c = g * CPG + (i >> 12);
        op[i] = (xp[i] - mean) * rstd * gamma[c] + beta[c];
    }
}

// ---------------------------------------------------------------------------
// conv1x1 via tf32 mma (unchanged from passing round).
// ---------------------------------------------------------------------------
__global__ __launch_bounds__(128) void conv_mma(const float* __restrict__ in,
                                                const float* __restrict__ w,
                                                const float* __restrict__ bias,
                                                const float* __restrict__ res,
                                                float* __restrict__ out) {
    __shared__ float Ws[64 * 36];
    __shared__ float Bs[32 * 72];
    int bn = blockIdx.x, bo = blockIdx.y, b = blockIdx.z;
    int tid = threadIdx.x, lane = tid & 31, warp = tid >> 5;
    int g = lane >> 2, c = lane & 3;
    int ow = warp * 16;
    const float* inp = in + (size_t)b * CC * NN + bn * 64;

    float acc[8][4] = {};
    for (int kt = 0; kt < CC; kt += 32) {
        __syncthreads();
        #pragma unroll
        for (int e = tid; e < 2048; e += 128) {
            int o = e >> 5, kk = e & 31;
            Ws[o * 36 + kk] = f2tff(w[(size_t)(bo * 64 + o) * CC + kt + kk]);
        }
        #pragma unroll
        for (int e = tid; e < 2048; e += 128) {
            int kk = e >> 6, n = e & 63;
            Bs[kk * 72 + n] = f2tff(inp[(size_t)(kt + kk) * NN + n]);
        }
        __syncthreads();
        #pragma unroll
        for (int ks = 0; ks < 4; ks++) {
            unsigned a0 = uf(Ws[(ow + g) * 36 + ks * 8 + c]);
            unsigned a1 = uf(Ws[(ow + g + 8) * 36 + ks * 8 + c]);
            unsigned a2 = uf(Ws[(ow + g) * 36 + ks * 8 + c + 4]);
            unsigned a3 = uf(Ws[(ow + g + 8) * 36 + ks * 8 + c + 4]);
            #pragma unroll
            for (int nt = 0; nt < 8; nt++) {
                unsigned b0 = uf(Bs[(ks * 8 + c) * 72 + nt * 8 + g]);
                unsigned b1 = uf(Bs[(ks * 8 + c + 4) * 72 + nt * 8 + g]);
                mma_tf32(acc[nt], a0, a1, a2, a3, b0, b1);
            }
        }
    }
    int o0 = bo * 64 + ow + g;
    float bi0 = bias[o0], bi1 = bias[o0 + 8];
    #pragma unroll
    for (int nt = 0; nt < 8; nt++) {
        int n = bn * 64 + nt * 8 + 2 * c;
        size_t i0 = ((size_t)b * CC + o0) * NN + n;
        size_t i1 = ((size_t)b * CC + o0 + 8) * NN + n;
        float2 v0 = make_float2(acc[nt][0] + bi0, acc[nt][1] + bi0);
        float2 v1 = make_float2(acc[nt][2] + bi1, acc[nt][3] + bi1);
        if (res) {
            float2 r0 = *(const float2*)&res[i0];
            float2 r1 = *(const float2*)&res[i1];
            v0.x += r0.x; v0.y += r0.y;
            v1.x += r1.x; v1.y += r1.y;
        }
        *(float2*)&out[i0] = v0;
        *(float2*)&out[i1] = v1;
    }
}

// ---------------------------------------------------------------------------
// Flash attention, bf16 mma (m16n8k16). Block = 128 queries x one head,
// 256 threads = 8 warps; warp owns 16 query rows x all 64 keys of a tile.
// Smem (uint words):
//   Qs2 [128 q][36]  (dp = d/2 pairs, bf16x2, pre-scaled)
//   Ks2 [32 dp][72]  (pairs along d, bf16x2)
//   Vs2 [64 d][36]   (pairs along m, bf16x2)
//   Os  reuses base  [64 d][132] fp32 staging
// ---------------------------------------------------------------------------
__global__ __launch_bounds__(256) void attn_mma(const float* __restrict__ q,
                                                const float* __restrict__ k,
                                                const float* __restrict__ v,
                                                float* __restrict__ out) {
    extern __shared__ unsigned smu[];
    unsigned* Qs2 = smu;                  // 128*36 = 4608
    unsigned* Ks2 = Qs2 + 128 * 36;       // 32*72  = 2304
    unsigned* Vs2 = Ks2 + 32 * 72;        // 64*36  = 2304
    float*    Os  = (float*)smu;          // 64*132 = 8448 fp32 (epilogue reuse)

    int nb = blockIdx.x, h = blockIdx.y, b = blockIdx.z;
    int tid = threadIdx.x, lane = tid & 31, warp = tid >> 5;
    int g = lane >> 2, c = lane & 3;
    int qw = warp * 16;
    size_t base = ((size_t)b * CC + h * HD) * NN;
    int n0 = nb * 128;

    // Load Q (scaled by 1/8), packed bf16x2 along d
    for (int e = tid; e < 32 * 128; e += 256) {
        int dp = e >> 7, qn = e & 127;
        float q0 = q[base + (size_t)(2 * dp) * NN + n0 + qn] * 0.125f;
        float q1 = q[base + (size_t)(2 * dp + 1) * NN + n0 + qn] * 0.125f;
        Qs2[qn * 36 + dp] = pk_bf2(q0, q1);
    }
    __syncthreads();

    // Persistent Q A-fragments: 4 k-steps of 16
    unsigned qa[4][4];
    #pragma unroll
    for (int kt = 0; kt < 4; kt++) {
        qa[kt][0] = Qs2[(qw + g) * 36 + kt * 8 + c];
        qa[kt][1] = Qs2[(qw + g + 8) * 36 + kt * 8 + c];
        qa[kt][2] = Qs2[(qw + g) * 36 + kt * 8 + 4 + c];
        qa[kt][3] = Qs2[(qw + g + 8) * 36 + kt * 8 + 4 + c];
    }

    float o[8][4] = {};
    float m0 = -1e30f, m1 = -1e30f, l0 = 0.f, l1 = 0.f;

    for (int mt = 0; mt < NN; mt += 64) {
        __syncthreads();
        // K: pairs along d -> Ks2[dp][m], stride 72 (store m-fast: conflict-free)
        for (int e = tid; e < 2048; e += 256) {
            int dp = e >> 6, mm = e & 63;
            float k0 = k[base + (size_t)(2 * dp) * NN + mt + mm];
            float k1 = k[base + (size_t)(2 * dp + 1) * NN + mt + mm];
            Ks2[dp * 72 + mm] = pk_bf2(k0, k1);
        }
        // V: pairs along m -> Vs2[d][mp], stride 36 (float2 gmem, mp-fast store)
        for (int e = tid; e < 2048; e += 256) {
            int d = e >> 5, mp = e & 31;
            float2 vv = *(const float2*)&v[base + (size_t)d * NN + mt + 2 * mp];
            Vs2[d * 36 + mp] = pk_bf2(vv.x, vv.y);
        }
        __syncthreads();

        // S = Q K^T : 4 ksteps x 8 ntiles
        float s[8][4] = {};
        #pragma unroll
        for (int kt = 0; kt < 4; kt++) {
            #pragma unroll
            for (int nt = 0; nt < 8; nt++) {
                unsigned b0 = Ks2[(kt * 8 + c) * 72 + nt * 8 + g];
                unsigned b1 = Ks2[(kt * 8 + 4 + c) * 72 + nt * 8 + g];
                mma_bf16(s[nt], qa[kt][0], qa[kt][1], qa[kt][2], qa[kt][3], b0, b1);
            }
        }

        // Online softmax (rows g, g+8; stats shared across the 4 c-lanes)
        float rmax0 = -1e30f, rmax1 = -1e30f;
        #pragma unroll
        for (int nt = 0; nt < 8; nt++) {
            rmax0 = fmaxf(rmax0, fmaxf(s[nt][0], s[nt][1]));
            rmax1 = fmaxf(rmax1, fmaxf(s[nt][2], s[nt][3]));
        }
        rmax0 = fmaxf(rmax0, __shfl_xor_sync(0xffffffffu, rmax0, 1));
        rmax0 = fmaxf(rmax0, __shfl_xor_sync(0xffffffffu, rmax0, 2));
        rmax1 = fmaxf(rmax1, __shfl_xor_sync(0xffffffffu, rmax1, 1));
        rmax1 = fmaxf(rmax1, __shfl_xor_sync(0xffffffffu, rmax1, 2));
        float nm0 = fmaxf(m0, rmax0), nm1 = fmaxf(m1, rmax1);
        float cor0 = __expf(m0 - nm0), cor1 = __expf(m1 - nm1);
        m0 = nm0; m1 = nm1;

        float rs0 = 0.f, rs1 = 0.f;
        unsigned pa[8][2];   // [ntile]{row g pair, row g+8 pair}
        #pragma unroll
        for (int nt = 0; nt < 8; nt++) {
            float p0 = __expf(s[nt][0] - nm0);
            float p1 = __expf(s[nt][1] - nm0);
            float p2 = __expf(s[nt][2] - nm1);
            float p3 = __expf(s[nt][3] - nm1);
            rs0 += p0 + p1; rs1 += p2 + p3;
            pa[nt][0] = pk_bf2(p0, p1);
            pa[nt][1] = pk_bf2(p2, p3);
        }
        rs0 += __shfl_xor_sync(0xffffffffu, rs0, 1);
        rs0 += __shfl_xor_sync(0xffffffffu, rs0, 2);
        rs1 += __shfl_xor_sync(0xffffffffu, rs1, 1);
        rs1 += __shfl_xor_sync(0xffffffffu, rs1, 2);
        l0 = l0 * cor0 + rs0;
        l1 = l1 * cor1 + rs1;
        #pragma unroll
        for (int nt = 0; nt < 8; nt++) {
            o[nt][0] *= cor0; o[nt][1] *= cor0;
            o[nt][2] *= cor1; o[nt][3] *= cor1;
        }

        // O += P V : 4 key-blocks of 16, A-frags come straight from pa[] pairs
        #pragma unroll
        for (int j = 0; j < 4; j++) {
            unsigned a0 = pa[2 * j][0];
            unsigned a1 = pa[2 * j][1];
            unsigned a2 = pa[2 * j + 1][0];
            unsigned a3 = pa[2 * j + 1][1];
            #pragma unroll
            for (int nt = 0; nt < 8; nt++) {
                unsigned b0 = Vs2[(nt * 8 + g) * 36 + j * 8 + c];
                unsigned b1 = Vs2[(nt * 8 + g) * 36 + j * 8 + 4 + c];
                mma_bf16(o[nt], a0, a1, a2, a3, b0, b1);
            }
        }
    }
    __syncthreads();

    // Normalize, stage d-major, coalesced writeback
    float inv0 = 1.f / l0, inv1 = 1.f / l1;
    #pragma unroll
    for (int nt = 0; nt < 8; nt++) {
        int d = nt * 8 + 2 * c;
        Os[d * 132 + qw + g]           = o[nt][0] * inv0;
        Os[(d + 1) * 132 + qw + g]     = o[nt][1] * inv0;
        Os[d * 132 + qw + g + 8]       = o[nt][2] * inv1;
        Os[(d + 1) * 132 + qw + g + 8] = o[nt][3] * inv1;
    }
    __syncthreads();
    for (int e = tid; e < 64 * 128; e += 256) {
        int d = e >> 7, qn = e & 127;
        out[base + (size_t)d * NN + n0 + qn] = Os[d * 132 + qn];
    }
}

// ---------------------------------------------------------------------------
extern "C" void kernel_launch(void* const* d_in, const int* in_sizes, int n_in,
                              void* d_out, int out_size) {
    const float* x      = (const float*)d_in[0];
    const float* cond   = (const float*)d_in[1];
    const float* gn_q_w = (const float*)d_in[2];
    const float* gn_q_b = (const float*)d_in[3];
    const float* gn_kv_w= (const float*)d_in[4];
    const float* gn_kv_b= (const float*)d_in[5];
    const float* wq     = (const float*)d_in[6];
    const float* bq     = (const float*)d_in[7];
    const float* wk     = (const float*)d_in[8];
    const float* bk     = (const float*)d_in[9];
    const float* wv     = (const float*)d_in[10];
    const float* bv     = (const float*)d_in[11];
    const float* wo     = (const float*)d_in[12];
    const float* bo     = (const float*)d_in[13];
    float* out = (float*)d_out;

    float *qin, *kvin, *qb, *kb, *vb, *attb;
    cudaGetSymbolAddress((void**)&qin,  g_qin);
    cudaGetSymbolAddress((void**)&kvin, g_kvin);
    cudaGetSymbolAddress((void**)&qb,   g_q);
    cudaGetSymbolAddress((void**)&kb,   g_k);
    cudaGetSymbolAddress((void**)&vb,   g_v);
    cudaGetSymbolAddress((void**)&attb, g_att);

    gn_kernel<<<BB * GROUPS, 256>>>(x,    gn_q_w,  gn_q_b,  qin);
    gn_kernel<<<BB * GROUPS, 256>>>(cond, gn_kv_w, gn_kv_b, kvin);

    dim3 cgrid(NN / 64, CC / 64, BB);
    conv_mma<<<cgrid, 128>>>(qin,  wq, bq, nullptr, qb);
    conv_mma<<<cgrid, 128>>>(kvin, wk, bk, nullptr, kb);
    conv_mma<<<cgrid, 128>>>(kvin, wv, bv, nullptr, vb);

    int smem = (128 * 36 + 32 * 72 + 64 * 36) * (int)sizeof(unsigned); // 36864 B
    cudaFuncSetAttribute(attn_mma, cudaFuncAttributeMaxDynamicSharedMemorySize, smem);
    dim3 agrid(NN / 128, NHEAD, BB);
    attn_mma<<<agrid, 256, smem>>>(qb, kb, vb, attb);

    conv_mma<<<cgrid, 128>>>(attb, wo, bo, x, out);
}